// round 12
// baseline (speedup 1.0000x reference)
#include <cuda_runtime.h>
#include <cstdint>

#define N_NODES 8192
#define F_DIM   256
#define MN      ((size_t)N_NODES * F_DIM)

// Persistent-G2 assignment: 2048 units = 64 tiles(128x256) x 32 kchunks(256).
// 148 CTAs (1/SM): first 124 own 14 units, last 24 own 13. (124*14+24*13=2048)
#define NCTA_P  148
#define BIGQ    1736     // 124*14

// Scratch (no cudaMalloc allowed)
__device__ float g_hT[(size_t)F_DIM * N_NODES];   // rna(neigh_W @ feat^T) [256][8192]
__device__ float g_agg[MN];                        // (adj@h)/deg, tf32-rounded
__device__ float g_feat[MN];                       // tf32-rounded features
__device__ float g_part[4 * MN];                   // per-slot partials (32MB)
__device__ float g_rowp[4 * N_NODES];              // per-slot partial rowsums

// ---------------------------------------------------------------------------
// helpers
// ---------------------------------------------------------------------------
__device__ __forceinline__ void cp_async16(uint32_t s, const void* g) {
    asm volatile("cp.async.cg.shared.global [%0], [%1], 16;\n" :: "r"(s), "l"(g));
}
__device__ __forceinline__ void cp_commit() { asm volatile("cp.async.commit_group;\n"); }
template <int N> __device__ __forceinline__ void cp_wait() {
    asm volatile("cp.async.wait_group %0;\n" :: "n"(N));
}
__device__ __forceinline__ float rna_tf32(float f) {
    uint32_t r;
    asm("cvt.rna.tf32.f32 %0, %1;\n" : "=r"(r) : "f"(f));
    return __uint_as_float(r);
}
__device__ __forceinline__ void mma_tf32(float* c, const uint32_t* a, const uint32_t* b) {
    asm volatile(
        "mma.sync.aligned.m16n8k8.row.col.f32.tf32.tf32.f32 "
        "{%0,%1,%2,%3}, {%4,%5,%6,%7}, {%8,%9}, {%0,%1,%2,%3};\n"
        : "+f"(c[0]), "+f"(c[1]), "+f"(c[2]), "+f"(c[3])
        : "r"(a[0]), "r"(a[1]), "r"(a[2]), "r"(a[3]), "r"(b[0]), "r"(b[1]));
}
__device__ __forceinline__ void ldsm_x4(uint32_t& r0, uint32_t& r1, uint32_t& r2,
                                        uint32_t& r3, uint32_t a) {
    asm volatile("ldmatrix.sync.aligned.m8n8.x4.shared.b16 {%0,%1,%2,%3}, [%4];\n"
                 : "=r"(r0), "=r"(r1), "=r"(r2), "=r"(r3) : "r"(a));
}
__device__ __forceinline__ int unit_owner(int u) {
    return (u < BIGQ) ? (u / 14) : (124 + (u - BIGQ) / 13);
}

// ---------------------------------------------------------------------------
__global__ void round_copy_kernel(const float* __restrict__ src, float* __restrict__ dst) {
    const size_t i = (size_t)(blockIdx.x * blockDim.x + threadIdx.x) * 4;
    float4 v = *reinterpret_cast<const float4*>(src + i);
    v.x = rna_tf32(v.x); v.y = rna_tf32(v.y);
    v.z = rna_tf32(v.z); v.w = rna_tf32(v.w);
    *reinterpret_cast<float4*>(dst + i) = v;
}

// zero slot 3 (slots 0-2 are always written by the persistent GEMM)
__global__ void zero_slot3_kernel(float* __restrict__ part, float* __restrict__ rowp) {
    const size_t g = (size_t)blockIdx.x * blockDim.x + threadIdx.x;
    *reinterpret_cast<float4*>(part + 3 * MN + g * 4) = make_float4(0, 0, 0, 0);
    if (g < N_NODES / 4)
        *reinterpret_cast<float4*>(rowp + 3 * N_NODES + g * 4) = make_float4(0, 0, 0, 0);
}

__global__ void reduce_big_kernel(const float* __restrict__ part,
                                  const float* __restrict__ rowp,
                                  float* __restrict__ agg) {
    const size_t i = (size_t)(blockIdx.x * blockDim.x + threadIdx.x) * 4;
    const int row = (int)(i >> 8);
    const float inv = 1.0f / (rowp[row] + rowp[N_NODES + row] +
                              rowp[2 * N_NODES + row] + rowp[3 * N_NODES + row] + 1.0f);
    float4 a = *reinterpret_cast<const float4*>(part + i);
    float4 b = *reinterpret_cast<const float4*>(part + MN + i);
    float4 c = *reinterpret_cast<const float4*>(part + 2 * MN + i);
    float4 d = *reinterpret_cast<const float4*>(part + 3 * MN + i);
    float4 o;
    o.x = rna_tf32((a.x + b.x + c.x + d.x) * inv);
    o.y = rna_tf32((a.y + b.y + c.y + d.y) * inv);
    o.z = rna_tf32((a.z + b.z + c.z + d.z) * inv);
    o.w = rna_tf32((a.w + b.w + c.w + d.w) * inv);
    *reinterpret_cast<float4*>(agg + i) = o;
}

// ---------------------------------------------------------------------------
// NARROW kernel: tile 128x128x32, 256 threads, 2 CTAs/SM (GEMM1 + concat GEMM3)
// ---------------------------------------------------------------------------
#define A_FLTS 4608              // 128*36
#define STAGE_FLTS_N (2 * A_FLTS)
#define NSTAGE_N 3
#define SMEM_N (NSTAGE_N * STAGE_FLTS_N * 4)   // 110592

template <bool CONCAT, bool ROUND_OUT>
__global__ __launch_bounds__(256, 2)
void tgemm(const float* __restrict__ A, const float* __restrict__ A2,
           const float* __restrict__ B, float* __restrict__ C,
           int K, int lda, int ldb, int ldc)
{
    extern __shared__ float sm[];
    const int tid  = threadIdx.x;
    const int lane = tid & 31;
    const int wid  = tid >> 5;
    const int wm   = wid & 1;
    const int wn   = wid >> 1;
    const int bm   = blockIdx.y * 128;
    const int bn   = blockIdx.x * 128;

    const uint32_t smem_base = (uint32_t)__cvta_generic_to_shared(sm);

    float acc[4][4][4];
    #pragma unroll
    for (int i = 0; i < 4; i++)
        #pragma unroll
        for (int j = 0; j < 4; j++)
            #pragma unroll
            for (int r = 0; r < 4; r++) acc[i][j][r] = 0.0f;

    uint32_t a_off, b_off;
    {
        const int ar = wm * 64 + (lane & 7) + ((lane >> 3) & 1) * 8;
        const int ak = ((lane >> 4) & 1) * 4;
        a_off = (uint32_t)(ar * 36 + ak) * 4u;
        const int br = wn * 32 + ((lane >> 4) & 1) * 8 + (lane & 7);
        const int bk = ((lane >> 3) & 1) * 4;
        b_off = (uint32_t)(br * 36 + bk) * 4u + A_FLTS * 4u;
    }

    const int a_r  = tid >> 3;
    const int a_kv = (tid & 7) * 4;

    auto fill = [&](int t) {
        const int k0 = t * 32;
        const int s  = t % NSTAGE_N;
        const uint32_t sA = smem_base + (uint32_t)(s * STAGE_FLTS_N) * 4u;
        const uint32_t sB = sA + A_FLTS * 4u;
        const float* Asrc = A;
        int ka = k0;
        if (CONCAT && k0 >= F_DIM) { Asrc = A2; ka = k0 - F_DIM; }
        #pragma unroll
        for (int p = 0; p < 4; p++) {
            const int r = a_r + 32 * p;
            cp_async16(sA + (uint32_t)(r * 36 + a_kv) * 4u,
                       Asrc + (size_t)(bm + r) * lda + ka + a_kv);
        }
        #pragma unroll
        for (int p = 0; p < 4; p++) {
            const int n = a_r + 32 * p;
            cp_async16(sB + (uint32_t)(n * 36 + a_kv) * 4u,
                       B + (size_t)(bn + n) * ldb + k0 + a_kv);
        }
    };

    const int T = K >> 5;
    fill(0); cp_commit();
    fill(1); cp_commit();

    for (int t = 0; t < T; t++) {
        cp_wait<1>();
        __syncthreads();
        if (t + 2 < T) fill(t + 2);
        cp_commit();

        const int s = t % NSTAGE_N;
        const uint32_t stage_b = smem_base + (uint32_t)(s * STAGE_FLTS_N) * 4u;
        const uint32_t a_base = stage_b + a_off;
        const uint32_t b_base = stage_b + b_off;

        #pragma unroll
        for (int k8 = 0; k8 < 32; k8 += 8) {
            const uint32_t kb = (uint32_t)k8 * 4u;
            uint32_t af[4][4];
            #pragma unroll
            for (int mi = 0; mi < 4; mi++)
                ldsm_x4(af[mi][0], af[mi][1], af[mi][2], af[mi][3],
                        a_base + kb + (uint32_t)(mi * 16 * 36) * 4u);
            uint32_t bf[4][2];
            #pragma unroll
            for (int pi = 0; pi < 2; pi++)
                ldsm_x4(bf[2 * pi][0], bf[2 * pi][1], bf[2 * pi + 1][0], bf[2 * pi + 1][1],
                        b_base + kb + (uint32_t)(pi * 16 * 36) * 4u);
            #pragma unroll
            for (int mi = 0; mi < 4; mi++)
                #pragma unroll
                for (int ni = 0; ni < 4; ni++)
                    mma_tf32(acc[mi][ni], af[mi], bf[ni]);
        }
    }

    #pragma unroll
    for (int mi = 0; mi < 4; mi++) {
        const int r0 = bm + wm * 64 + mi * 16 + (lane >> 2);
        #pragma unroll
        for (int ni = 0; ni < 4; ni++) {
            const int c0 = bn + wn * 32 + ni * 8 + 2 * (lane & 3);
            float* p0 = C + (size_t)r0 * ldc + c0;
            float* p1 = C + (size_t)(r0 + 8) * ldc + c0;
            float2 v0 = make_float2(acc[mi][ni][0], acc[mi][ni][1]);
            float2 v1 = make_float2(acc[mi][ni][2], acc[mi][ni][3]);
            if (ROUND_OUT) {
                v0.x = rna_tf32(v0.x); v0.y = rna_tf32(v0.y);
                v1.x = rna_tf32(v1.x); v1.y = rna_tf32(v1.y);
            }
            *reinterpret_cast<float2*>(p0) = v0;
            *reinterpret_cast<float2*>(p1) = v1;
        }
    }
}

// ---------------------------------------------------------------------------
// PERSISTENT big GEMM: 148 CTAs, CTA tile 128x256, 8 warps (2x4), warp tile
// 64x64. Fragment redundancy halved vs 128x128 (A x4, B x2 -> A x4? no:
// A shared by 4 wn-warps, B by 2 wm-warps; per-MAC LDSM bytes 0.19 -> 0.12).
// Rowsum computed from A FRAGMENTS (no extra LDS). adj read once (single bn).
// NSTAGE=4 ring of 54KB stages = 216KB smem, 1 CTA/SM, full reg budget.
// ---------------------------------------------------------------------------
#define B_FLTS_P (256 * 36)                       // 9216
#define STAGE_FLTS_P (A_FLTS + B_FLTS_P)          // 13824
#define NSTAGE_P 4
#define SMEM_P (NSTAGE_P * STAGE_FLTS_P * 4)      // 221184

__global__ __launch_bounds__(256, 1)
void tgemm_persist(const float* __restrict__ A, const float* __restrict__ B,
                   float* __restrict__ part, float* __restrict__ rowp)
{
    extern __shared__ float sm[];

    const int cta  = blockIdx.x;                  // 0..147
    int u          = (cta < 124) ? 14 * cta : BIGQ + 13 * (cta - 124);
    const int uend = u + ((cta < 124) ? 14 : 13);

    const int tid  = threadIdx.x;
    const int lane = tid & 31;
    const int wid  = tid >> 5;
    const int wm   = wid & 1;      // 2 warp rows (64 each)
    const int wn   = wid >> 1;     // 4 warp cols (64 each)

    const uint32_t smem_base = (uint32_t)__cvta_generic_to_shared(sm);

    uint32_t a_off, b_off;
    {
        const int ar = wm * 64 + (lane & 7) + ((lane >> 3) & 1) * 8;
        const int ak = ((lane >> 4) & 1) * 4;
        a_off = (uint32_t)(ar * 36 + ak) * 4u;
        const int br = wn * 64 + ((lane >> 4) & 1) * 8 + (lane & 7);
        const int bk = ((lane >> 3) & 1) * 4;
        b_off = (uint32_t)(br * 36 + bk) * 4u + A_FLTS * 4u;
    }
    const int l_r  = tid >> 3;          // 0..31
    const int l_kv = (tid & 7) * 4;     // 0..28

    while (u < uend) {
        const int tile   = u >> 5;                    // 0..63
        const int kc0    = u & 31;
        const int runlen = min(uend - u, 32 - kc0);
        const int slot   = cta - unit_owner(tile << 5);   // 0..3
        const int bm     = tile * 128;
        const int kbeg   = kc0 * 256;
        const int T      = runlen * 8;                // stages of K=32

        float acc[4][8][4];
        #pragma unroll
        for (int i = 0; i < 4; i++)
            #pragma unroll
            for (int j = 0; j < 8; j++)
                #pragma unroll
                for (int r = 0; r < 4; r++) acc[i][j][r] = 0.0f;
        float rs[4][2];
        #pragma unroll
        for (int i = 0; i < 4; i++) { rs[i][0] = 0.0f; rs[i][1] = 0.0f; }

        auto fill = [&](int t) {
            const int k0 = kbeg + t * 32;
            const int s  = t & (NSTAGE_P - 1);
            const uint32_t sA = smem_base + (uint32_t)(s * STAGE_FLTS_P) * 4u;
            const uint32_t sB = sA + A_FLTS * 4u;
            #pragma unroll
            for (int p = 0; p < 4; p++) {
                const int r = l_r + 32 * p;
                cp_async16(sA + (uint32_t)(r * 36 + l_kv) * 4u,
                           A + (size_t)(bm + r) * N_NODES + k0 + l_kv);
            }
            #pragma unroll
            for (int p = 0; p < 8; p++) {
                const int n = l_r + 32 * p;
                cp_async16(sB + (uint32_t)(n * 36 + l_kv) * 4u,
                           B + (size_t)n * N_NODES + k0 + l_kv);
            }
        };

        fill(0); cp_commit();
        fill(1); cp_commit();
        fill(2); cp_commit();

        for (int t = 0; t < T; t++) {
            cp_wait<2>();
            __syncthreads();          // data ready; prev reads of slot (t+3)&3 done
            if (t + 3 < T) fill(t + 3);
            cp_commit();

            const int s = t & (NSTAGE_P - 1);
            const uint32_t stage_b = smem_base + (uint32_t)(s * STAGE_FLTS_P) * 4u;
            const uint32_t a_base = stage_b + a_off;
            const uint32_t b_base = stage_b + b_off;

            #pragma unroll
            for (int k8 = 0; k8 < 32; k8 += 8) {
                const uint32_t kb = (uint32_t)k8 * 4u;
                uint32_t af[4][4];
                #pragma unroll
                for (int mi = 0; mi < 4; mi++)
                    ldsm_x4(af[mi][0], af[mi][1], af[mi][2], af[mi][3],
                            a_base + kb + (uint32_t)(mi * 16 * 36) * 4u);
                uint32_t bf[8][2];
                #pragma unroll
                for (int pi = 0; pi < 4; pi++)
                    ldsm_x4(bf[2 * pi][0], bf[2 * pi][1],
                            bf[2 * pi + 1][0], bf[2 * pi + 1][1],
                            b_base + kb + (uint32_t)(pi * 16 * 36) * 4u);
                #pragma unroll
                for (int mi = 0; mi < 4; mi++)
                    #pragma unroll
                    for (int ni = 0; ni < 8; ni++)
                        mma_tf32(acc[mi][ni], af[mi], bf[ni]);
                // rowsum from A fragments (af holds raw fp32 adj values):
                // rows (lane>>2)+16mi+64wm (+8 for odd regs), k covered fully.
                #pragma unroll
                for (int mi = 0; mi < 4; mi++) {
                    rs[mi][0] += __uint_as_float(af[mi][0]) + __uint_as_float(af[mi][2]);
                    rs[mi][1] += __uint_as_float(af[mi][1]) + __uint_as_float(af[mi][3]);
                }
            }
        }

        __syncthreads();    // all warps done reading ring before next run refill

        // quad-reduce rowsums (lanes 4r..4r+3 hold same rows), wn==0 writes
        #pragma unroll
        for (int mi = 0; mi < 4; mi++) {
            #pragma unroll
            for (int j = 0; j < 2; j++) {
                rs[mi][j] += __shfl_xor_sync(0xffffffffu, rs[mi][j], 1);
                rs[mi][j] += __shfl_xor_sync(0xffffffffu, rs[mi][j], 2);
            }
        }
        if (wn == 0 && (lane & 3) == 0) {
            const int r = lane >> 2;   // 0..7
            #pragma unroll
            for (int mi = 0; mi < 4; mi++) {
                rowp[slot * N_NODES + bm + wm * 64 + mi * 16 + r]     = rs[mi][0];
                rowp[slot * N_NODES + bm + wm * 64 + mi * 16 + 8 + r] = rs[mi][1];
            }
        }

        float* C = part + (size_t)slot * MN;
        #pragma unroll
        for (int mi = 0; mi < 4; mi++) {
            const int r0 = bm + wm * 64 + mi * 16 + (lane >> 2);
            #pragma unroll
            for (int ni = 0; ni < 8; ni++) {
                const int c0 = wn * 64 + ni * 8 + 2 * (lane & 3);
                *reinterpret_cast<float2*>(C + (size_t)r0 * F_DIM + c0) =
                    make_float2(acc[mi][ni][0], acc[mi][ni][1]);
                *reinterpret_cast<float2*>(C + (size_t)(r0 + 8) * F_DIM + c0) =
                    make_float2(acc[mi][ni][2], acc[mi][ni][3]);
            }
        }

        u += runlen;
    }
}

// ---------------------------------------------------------------------------
extern "C" void kernel_launch(void* const* d_in, const int* in_sizes, int n_in,
                              void* d_out, int out_size)
{
    const float* features = (const float*)d_in[0];  // [8192, 256]
    const float* adj      = (const float*)d_in[1];  // [8192, 8192]
    const float* neigh_W  = (const float*)d_in[2];  // [256, 256]
    const float* lin_W    = (const float*)d_in[3];  // [256, 512]
    float* out = (float*)d_out;                     // [8192, 256]

    float *hT, *agg, *feat, *part, *rowp;
    cudaGetSymbolAddress((void**)&hT,   g_hT);
    cudaGetSymbolAddress((void**)&agg,  g_agg);
    cudaGetSymbolAddress((void**)&feat, g_feat);
    cudaGetSymbolAddress((void**)&part, g_part);
    cudaGetSymbolAddress((void**)&rowp, g_rowp);

    cudaFuncSetAttribute(tgemm<false, true >,
                         cudaFuncAttributeMaxDynamicSharedMemorySize, SMEM_N);
    cudaFuncSetAttribute(tgemm<true,  false>,
                         cudaFuncAttributeMaxDynamicSharedMemorySize, SMEM_N);
    cudaFuncSetAttribute(tgemm_persist,
                         cudaFuncAttributeMaxDynamicSharedMemorySize, SMEM_P);

    // 1) feat = round_tf32(features)
    round_copy_kernel<<<1024, 512>>>(features, feat);

    // 2) hT = rna(neigh_W @ feat^T)   M=256, N=8192, K=256
    tgemm<false, true><<<dim3(64, 2), 256, SMEM_N>>>(
        neigh_W, nullptr, feat, hT, F_DIM, F_DIM, F_DIM, N_NODES);

    // 3) zero slot 3 (only conditionally-written slot)
    zero_slot3_kernel<<<2048, 256>>>(part, rowp);

    // 4) persistent balanced adj @ hT^T partials (+ fragment rowsums), 148 CTAs
    tgemm_persist<<<NCTA_P, 256, SMEM_P>>>(adj, hT, part, rowp);

    // 5) agg = rna( (sum of 4 slots) / (sum rowsums + 1) )
    reduce_big_kernel<<<2048, 256>>>(part, rowp, agg);

    // 6) out = [feat | agg] @ lin_W^T   (single-pass concat, K=512)
    tgemm<true, false><<<dim3(2, 64), 256, SMEM_N>>>(
        feat, agg, lin_W, out, 2 * F_DIM, F_DIM, 2 * F_DIM, F_DIM);
}

// round 13
// speedup vs baseline: 1.0326x; 1.0326x over previous
#include <cuda_runtime.h>
#include <cstdint>

#define N_NODES 8192
#define F_DIM   256
#define MN      ((size_t)N_NODES * F_DIM)

// Persistent-G2 work assignment: 2048 units = 128 tiles x 16 k-chunks(512).
// 296 CTAs: first 272 own 7 units, last 24 own 6. (272*7 + 24*6 = 2048)
#define NCTA_P   296
#define BIGQ     1904     // 272*7

// Scratch (no cudaMalloc allowed)
__device__ float g_hT[(size_t)F_DIM * N_NODES];   // rna(neigh_W @ feat^T) [256][8192]
__device__ float g_agg[MN];                        // (adj@h)/deg, tf32-rounded
__device__ float g_feat[MN];                       // tf32-rounded features
__device__ float g_part[4 * MN];                   // per-slot partials (32MB)
__device__ float g_rowp[4 * N_NODES];              // per-slot partial rowsums

// ---------------------------------------------------------------------------
// helpers
// ---------------------------------------------------------------------------
__device__ __forceinline__ void cp_async16(uint32_t s, const void* g) {
    asm volatile("cp.async.cg.shared.global [%0], [%1], 16;\n" :: "r"(s), "l"(g));
}
__device__ __forceinline__ void cp_commit() { asm volatile("cp.async.commit_group;\n"); }
template <int N> __device__ __forceinline__ void cp_wait() {
    asm volatile("cp.async.wait_group %0;\n" :: "n"(N));
}
__device__ __forceinline__ float rna_tf32(float f) {
    uint32_t r;
    asm("cvt.rna.tf32.f32 %0, %1;\n" : "=r"(r) : "f"(f));
    return __uint_as_float(r);
}
__device__ __forceinline__ void mma_tf32(float* c, const uint32_t* a, const uint32_t* b) {
    asm volatile(
        "mma.sync.aligned.m16n8k8.row.col.f32.tf32.tf32.f32 "
        "{%0,%1,%2,%3}, {%4,%5,%6,%7}, {%8,%9}, {%0,%1,%2,%3};\n"
        : "+f"(c[0]), "+f"(c[1]), "+f"(c[2]), "+f"(c[3])
        : "r"(a[0]), "r"(a[1]), "r"(a[2]), "r"(a[3]), "r"(b[0]), "r"(b[1]));
}
__device__ __forceinline__ void ldsm_x4(uint32_t& r0, uint32_t& r1, uint32_t& r2,
                                        uint32_t& r3, uint32_t a) {
    asm volatile("ldmatrix.sync.aligned.m8n8.x4.shared.b16 {%0,%1,%2,%3}, [%4];\n"
                 : "=r"(r0), "=r"(r1), "=r"(r2), "=r"(r3) : "r"(a));
}
__device__ __forceinline__ int unit_owner(int u) {
    return (u < BIGQ) ? (u / 7) : (272 + (u - BIGQ) / 6);
}

// ---------------------------------------------------------------------------
__global__ void round_copy_kernel(const float* __restrict__ src, float* __restrict__ dst) {
    const size_t i = (size_t)(blockIdx.x * blockDim.x + threadIdx.x) * 4;
    float4 v = *reinterpret_cast<const float4*>(src + i);
    v.x = rna_tf32(v.x); v.y = rna_tf32(v.y);
    v.z = rna_tf32(v.z); v.w = rna_tf32(v.w);
    *reinterpret_cast<float4*>(dst + i) = v;
}

// zero slot 3 of part + rowp (slots 0-2 always written by the persistent GEMM)
__global__ void zero_slot3_kernel(float* __restrict__ part, float* __restrict__ rowp) {
    const size_t g = (size_t)blockIdx.x * blockDim.x + threadIdx.x;
    *reinterpret_cast<float4*>(part + 3 * MN + g * 4) = make_float4(0, 0, 0, 0);
    if (g < N_NODES / 4)
        *reinterpret_cast<float4*>(rowp + 3 * N_NODES + g * 4) = make_float4(0, 0, 0, 0);
}

__global__ void reduce_big_kernel(const float* __restrict__ part,
                                  const float* __restrict__ rowp,
                                  float* __restrict__ agg) {
    const size_t i = (size_t)(blockIdx.x * blockDim.x + threadIdx.x) * 4;
    const int row = (int)(i >> 8);
    const float inv = 1.0f / (rowp[row] + rowp[N_NODES + row] +
                              rowp[2 * N_NODES + row] + rowp[3 * N_NODES + row] + 1.0f);
    float4 a = *reinterpret_cast<const float4*>(part + i);
    float4 b = *reinterpret_cast<const float4*>(part + MN + i);
    float4 c = *reinterpret_cast<const float4*>(part + 2 * MN + i);
    float4 d = *reinterpret_cast<const float4*>(part + 3 * MN + i);
    float4 o;
    o.x = rna_tf32((a.x + b.x + c.x + d.x) * inv);
    o.y = rna_tf32((a.y + b.y + c.y + d.y) * inv);
    o.z = rna_tf32((a.z + b.z + c.z + d.z) * inv);
    o.w = rna_tf32((a.w + b.w + c.w + d.w) * inv);
    *reinterpret_cast<float4*>(agg + i) = o;
}

// ---------------------------------------------------------------------------
// NARROW kernel: tile 128x128x32, 256 threads, 2 CTAs/SM (GEMM1 + concat GEMM3)
// ---------------------------------------------------------------------------
#define A_FLTS 4608              // 128*36
#define STAGE_FLTS_N (2 * A_FLTS)
#define NSTAGE 3
#define SMEM_N (NSTAGE * STAGE_FLTS_N * 4)   // 110592

template <bool CONCAT, bool ROUND_OUT>
__global__ __launch_bounds__(256, 2)
void tgemm(const float* __restrict__ A, const float* __restrict__ A2,
           const float* __restrict__ B, float* __restrict__ C,
           int K, int lda, int ldb, int ldc)
{
    extern __shared__ float sm[];
    const int tid  = threadIdx.x;
    const int lane = tid & 31;
    const int wid  = tid >> 5;
    const int wm   = wid & 1;
    const int wn   = wid >> 1;
    const int bm   = blockIdx.y * 128;
    const int bn   = blockIdx.x * 128;

    const uint32_t smem_base = (uint32_t)__cvta_generic_to_shared(sm);

    float acc[4][4][4];
    #pragma unroll
    for (int i = 0; i < 4; i++)
        #pragma unroll
        for (int j = 0; j < 4; j++)
            #pragma unroll
            for (int r = 0; r < 4; r++) acc[i][j][r] = 0.0f;

    uint32_t a_off, b_off;
    {
        const int ar = wm * 64 + (lane & 7) + ((lane >> 3) & 1) * 8;
        const int ak = ((lane >> 4) & 1) * 4;
        a_off = (uint32_t)(ar * 36 + ak) * 4u;
        const int br = wn * 32 + ((lane >> 4) & 1) * 8 + (lane & 7);
        const int bk = ((lane >> 3) & 1) * 4;
        b_off = (uint32_t)(br * 36 + bk) * 4u + A_FLTS * 4u;
    }

    const int a_r  = tid >> 3;
    const int a_kv = (tid & 7) * 4;

    auto fill = [&](int t) {
        const int k0 = t * 32;
        const int s  = t % NSTAGE;
        const uint32_t sA = smem_base + (uint32_t)(s * STAGE_FLTS_N) * 4u;
        const uint32_t sB = sA + A_FLTS * 4u;
        const float* Asrc = A;
        int ka = k0;
        if (CONCAT && k0 >= F_DIM) { Asrc = A2; ka = k0 - F_DIM; }
        #pragma unroll
        for (int p = 0; p < 4; p++) {
            const int r = a_r + 32 * p;
            cp_async16(sA + (uint32_t)(r * 36 + a_kv) * 4u,
                       Asrc + (size_t)(bm + r) * lda + ka + a_kv);
        }
        #pragma unroll
        for (int p = 0; p < 4; p++) {
            const int n = a_r + 32 * p;
            cp_async16(sB + (uint32_t)(n * 36 + a_kv) * 4u,
                       B + (size_t)(bn + n) * ldb + k0 + a_kv);
        }
    };

    const int T = K >> 5;
    fill(0); cp_commit();
    fill(1); cp_commit();

    for (int t = 0; t < T; t++) {
        cp_wait<1>();
        __syncthreads();
        if (t + 2 < T) fill(t + 2);
        cp_commit();

        const int s = t % NSTAGE;
        const uint32_t stage_b = smem_base + (uint32_t)(s * STAGE_FLTS_N) * 4u;
        const uint32_t a_base = stage_b + a_off;
        const uint32_t b_base = stage_b + b_off;

        #pragma unroll
        for (int k8 = 0; k8 < 32; k8 += 8) {
            const uint32_t kb = (uint32_t)k8 * 4u;
            uint32_t af[4][4];
            #pragma unroll
            for (int mi = 0; mi < 4; mi++)
                ldsm_x4(af[mi][0], af[mi][1], af[mi][2], af[mi][3],
                        a_base + kb + (uint32_t)(mi * 16 * 36) * 4u);
            uint32_t bf[4][2];
            #pragma unroll
            for (int pi = 0; pi < 2; pi++)
                ldsm_x4(bf[2 * pi][0], bf[2 * pi][1], bf[2 * pi + 1][0], bf[2 * pi + 1][1],
                        b_base + kb + (uint32_t)(pi * 16 * 36) * 4u);
            #pragma unroll
            for (int mi = 0; mi < 4; mi++)
                #pragma unroll
                for (int ni = 0; ni < 4; ni++)
                    mma_tf32(acc[mi][ni], af[mi], bf[ni]);
        }
    }

    #pragma unroll
    for (int mi = 0; mi < 4; mi++) {
        const int r0 = bm + wm * 64 + mi * 16 + (lane >> 2);
        #pragma unroll
        for (int ni = 0; ni < 4; ni++) {
            const int c0 = bn + wn * 32 + ni * 8 + 2 * (lane & 3);
            float* p0 = C + (size_t)r0 * ldc + c0;
            float* p1 = C + (size_t)(r0 + 8) * ldc + c0;
            float2 v0 = make_float2(acc[mi][ni][0], acc[mi][ni][1]);
            float2 v1 = make_float2(acc[mi][ni][2], acc[mi][ni][3]);
            if (ROUND_OUT) {
                v0.x = rna_tf32(v0.x); v0.y = rna_tf32(v0.y);
                v1.x = rna_tf32(v1.x); v1.y = rna_tf32(v1.y);
            }
            *reinterpret_cast<float2*>(p0) = v0;
            *reinterpret_cast<float2*>(p1) = v1;
        }
    }
}

// ---------------------------------------------------------------------------
// PERSISTENT big GEMM: 296 CTAs, 2 CTAs/SM, tile 128x128, 8 warps (2x4,
// warp tile 64x32) — the R10 occupancy-optimal chassis. Rowsum now computed
// from A FRAGMENTS (af regs hold raw adj fp32), bn==0 tiles only: deletes the
// 16KB/stage smem re-read and the fma work on bn==1 CTAs.
// ---------------------------------------------------------------------------
__global__ __launch_bounds__(256, 2)
void tgemm_persist(const float* __restrict__ A, const float* __restrict__ B,
                   float* __restrict__ part, float* __restrict__ rowp)
{
    extern __shared__ float sm[];

    const int cta  = blockIdx.x;                      // 0..295
    int u          = (cta < 272) ? 7 * cta : BIGQ + 6 * (cta - 272);
    const int uend = u + ((cta < 272) ? 7 : 6);

    const int tid  = threadIdx.x;
    const int lane = tid & 31;
    const int wid  = tid >> 5;
    const int wm   = wid & 1;
    const int wn   = wid >> 1;

    const uint32_t smem_base = (uint32_t)__cvta_generic_to_shared(sm);

    uint32_t a_off, b_off;
    {
        const int ar = wm * 64 + (lane & 7) + ((lane >> 3) & 1) * 8;
        const int ak = ((lane >> 4) & 1) * 4;
        a_off = (uint32_t)(ar * 36 + ak) * 4u;
        const int br = wn * 32 + ((lane >> 4) & 1) * 8 + (lane & 7);
        const int bk = ((lane >> 3) & 1) * 4;
        b_off = (uint32_t)(br * 36 + bk) * 4u + A_FLTS * 4u;
    }
    const int a_r  = tid >> 3;
    const int a_kv = (tid & 7) * 4;

    while (u < uend) {
        const int tile   = u >> 4;
        const int kc0    = u & 15;
        const int runlen = min(uend - u, 16 - kc0);
        const int slot   = cta - unit_owner(tile << 4);   // 0..3
        const int bm     = (tile & 63) * 128;
        const int bn     = (tile >> 6) * 128;
        const int kbeg   = kc0 * 512;
        const int T      = runlen * 16;                   // stages of K=32
        const bool do_rs = (bn == 0);

        float acc[4][4][4];
        #pragma unroll
        for (int i = 0; i < 4; i++)
            #pragma unroll
            for (int j = 0; j < 4; j++)
                #pragma unroll
                for (int r = 0; r < 4; r++) acc[i][j][r] = 0.0f;
        float rs[4][2];
        #pragma unroll
        for (int i = 0; i < 4; i++) { rs[i][0] = 0.0f; rs[i][1] = 0.0f; }

        auto fill = [&](int t) {
            const int k0 = kbeg + t * 32;
            const int s  = t % NSTAGE;
            const uint32_t sA = smem_base + (uint32_t)(s * STAGE_FLTS_N) * 4u;
            const uint32_t sB = sA + A_FLTS * 4u;
            #pragma unroll
            for (int p = 0; p < 4; p++) {
                const int r = a_r + 32 * p;
                cp_async16(sA + (uint32_t)(r * 36 + a_kv) * 4u,
                           A + (size_t)(bm + r) * N_NODES + k0 + a_kv);
            }
            #pragma unroll
            for (int p = 0; p < 4; p++) {
                const int n = a_r + 32 * p;
                cp_async16(sB + (uint32_t)(n * 36 + a_kv) * 4u,
                           B + (size_t)(bn + n) * N_NODES + k0 + a_kv);
            }
        };

        fill(0); cp_commit();
        fill(1); cp_commit();

        for (int t = 0; t < T; t++) {
            cp_wait<1>();
            __syncthreads();
            if (t + 2 < T) fill(t + 2);
            cp_commit();

            const int s = t % NSTAGE;
            const uint32_t stage_b = smem_base + (uint32_t)(s * STAGE_FLTS_N) * 4u;
            const uint32_t a_base = stage_b + a_off;
            const uint32_t b_base = stage_b + b_off;

            #pragma unroll
            for (int k8 = 0; k8 < 32; k8 += 8) {
                const uint32_t kb = (uint32_t)k8 * 4u;
                uint32_t af[4][4];
                #pragma unroll
                for (int mi = 0; mi < 4; mi++)
                    ldsm_x4(af[mi][0], af[mi][1], af[mi][2], af[mi][3],
                            a_base + kb + (uint32_t)(mi * 16 * 36) * 4u);
                uint32_t bf[4][2];
                #pragma unroll
                for (int pi = 0; pi < 2; pi++)
                    ldsm_x4(bf[2 * pi][0], bf[2 * pi][1],
                            bf[2 * pi + 1][0], bf[2 * pi + 1][1],
                            b_base + kb + (uint32_t)(pi * 16 * 36) * 4u);
                #pragma unroll
                for (int mi = 0; mi < 4; mi++)
                    #pragma unroll
                    for (int ni = 0; ni < 4; ni++)
                        mma_tf32(acc[mi][ni], af[mi], bf[ni]);
                // rowsum from A fragments (af = raw fp32 adj values):
                // regs 0/2 -> row wm*64+mi*16+(lane>>2), regs 1/3 -> +8;
                // the quad (lanes xor 1,2) covers the full k8.
                if (do_rs) {
                    #pragma unroll
                    for (int mi = 0; mi < 4; mi++) {
                        rs[mi][0] += __uint_as_float(af[mi][0]) + __uint_as_float(af[mi][2]);
                        rs[mi][1] += __uint_as_float(af[mi][1]) + __uint_as_float(af[mi][3]);
                    }
                }
            }
        }

        __syncthreads();    // all warps done reading the ring before next run

        if (do_rs) {
            #pragma unroll
            for (int mi = 0; mi < 4; mi++) {
                #pragma unroll
                for (int j = 0; j < 2; j++) {
                    rs[mi][j] += __shfl_xor_sync(0xffffffffu, rs[mi][j], 1);
                    rs[mi][j] += __shfl_xor_sync(0xffffffffu, rs[mi][j], 2);
                }
            }
            if (wn == 0 && (lane & 3) == 0) {
                const int r = lane >> 2;   // 0..7
                #pragma unroll
                for (int mi = 0; mi < 4; mi++) {
                    rowp[slot * N_NODES + bm + wm * 64 + mi * 16 + r]     = rs[mi][0];
                    rowp[slot * N_NODES + bm + wm * 64 + mi * 16 + 8 + r] = rs[mi][1];
                }
            }
        }

        float* C = part + (size_t)slot * MN;
        #pragma unroll
        for (int mi = 0; mi < 4; mi++) {
            const int r0 = bm + wm * 64 + mi * 16 + (lane >> 2);
            #pragma unroll
            for (int ni = 0; ni < 4; ni++) {
                const int c0 = bn + wn * 32 + ni * 8 + 2 * (lane & 3);
                *reinterpret_cast<float2*>(C + (size_t)r0 * F_DIM + c0) =
                    make_float2(acc[mi][ni][0], acc[mi][ni][1]);
                *reinterpret_cast<float2*>(C + (size_t)(r0 + 8) * F_DIM + c0) =
                    make_float2(acc[mi][ni][2], acc[mi][ni][3]);
            }
        }

        u += runlen;
    }
}

// ---------------------------------------------------------------------------
extern "C" void kernel_launch(void* const* d_in, const int* in_sizes, int n_in,
                              void* d_out, int out_size)
{
    const float* features = (const float*)d_in[0];  // [8192, 256]
    const float* adj      = (const float*)d_in[1];  // [8192, 8192]
    const float* neigh_W  = (const float*)d_in[2];  // [256, 256]
    const float* lin_W    = (const float*)d_in[3];  // [256, 512]
    float* out = (float*)d_out;                     // [8192, 256]

    float *hT, *agg, *feat, *part, *rowp;
    cudaGetSymbolAddress((void**)&hT,   g_hT);
    cudaGetSymbolAddress((void**)&agg,  g_agg);
    cudaGetSymbolAddress((void**)&feat, g_feat);
    cudaGetSymbolAddress((void**)&part, g_part);
    cudaGetSymbolAddress((void**)&rowp, g_rowp);

    cudaFuncSetAttribute(tgemm<false, true >,
                         cudaFuncAttributeMaxDynamicSharedMemorySize, SMEM_N);
    cudaFuncSetAttribute(tgemm<true,  false>,
                         cudaFuncAttributeMaxDynamicSharedMemorySize, SMEM_N);
    cudaFuncSetAttribute(tgemm_persist,
                         cudaFuncAttributeMaxDynamicSharedMemorySize, SMEM_N);

    // 1) feat = round_tf32(features)
    round_copy_kernel<<<1024, 512>>>(features, feat);

    // 2) hT = rna(neigh_W @ feat^T)   M=256, N=8192, K=256
    tgemm<false, true><<<dim3(64, 2), 256, SMEM_N>>>(
        neigh_W, nullptr, feat, hT, F_DIM, F_DIM, F_DIM, N_NODES);

    // 3) zero slot 3 (only conditionally-written slot)
    zero_slot3_kernel<<<2048, 256>>>(part, rowp);

    // 4) persistent balanced adj @ hT^T partials (+ fragment rowsums), 296 CTAs
    tgemm_persist<<<NCTA_P, 256, SMEM_N>>>(adj, hT, part, rowp);

    // 5) agg = rna( (sum of 4 slots) / (sum rowsums + 1) )
    reduce_big_kernel<<<2048, 256>>>(part, rowp, agg);

    // 6) out = [feat | agg] @ lin_W^T   (single-pass concat, K=512)
    tgemm<true, false><<<dim3(2, 64), 256, SMEM_N>>>(
        feat, agg, lin_W, out, 2 * F_DIM, F_DIM, 2 * F_DIM, F_DIM);
}